// round 6
// baseline (speedup 1.0000x reference)
#include <cuda_runtime.h>
#include <cuda_fp16.h>
#include <cstdint>
#include <cfloat>

#define NB  128
#define PTS 2048
#define CIN 256

// ---- smem word (uint32) offsets ----
#define BH_W   0                      // W1 fp16: 17 k16-blocks * 256 n * 8 words
#define FB_W   34816                  // A fp16 operand, 2 bufs * 128 rows * 24 words
#define TL_W   40960                  // tail A fp16: 128 rows * 8 words
#define ST_W   41984                  // fp32 stage ring: 3 * 128 rows * 36 words
#define RED_W  55808                  // 1024 floats (also centroid scratch)
#define CEN_W  56832
#define SMEM_WORDS 56840
#define SMEM_BYTES (SMEM_WORDS * 4)   // 227360 B

__device__ float g_agg[NB * 256];

__device__ __forceinline__ uint32_t smem_u32(const void* p) {
    uint32_t a;
    asm("{ .reg .u64 t; cvta.to.shared.u64 t, %1; cvt.u32.u64 %0, t; }" : "=r"(a) : "l"(p));
    return a;
}
#define CP16(dst, src) asm volatile("cp.async.cg.shared.global [%0], [%1], 16;" :: "r"(dst), "l"(src) : "memory")
#define CPC()   asm volatile("cp.async.commit_group;" ::: "memory")
#define CPW(n)  asm volatile("cp.async.wait_group %0;" :: "n"(n) : "memory")

#define MMA16(c, a, b)                                                          \
    asm volatile("mma.sync.aligned.m16n8k16.row.col.f32.f16.f16.f32 "           \
        "{%0,%1,%2,%3}, {%4,%5,%6,%7}, {%8,%9}, {%0,%1,%2,%3};\n"               \
        : "+f"((c)[0]), "+f"((c)[1]), "+f"((c)[2]), "+f"((c)[3])                \
        : "r"((a)[0]), "r"((a)[1]), "r"((a)[2]), "r"((a)[3]),                   \
          "r"((b).x), "r"((b).y))

// ==================== fused: centroid + GEMM1(fp16 mma) + relu + seg-max ====================
// 1 CTA per scene. 512 threads = 16 warps: 4 M-warps x 4 N-warps; warp tile 32x64.
// K layout: 16 k16-blocks of feature + 1 tail block (rel-pos k256..258, zero pad).
// fp16 k-perm within a 16-block: pos(k) = ((k&7)>>1)*4 + ((k>>3)&1)*2 + (k&1)
// so (k, k+1, k+8, k+9) are 4 consecutive halves -> one LDS.64 per mma fragment pair.
__global__ __launch_bounds__(512, 1)
void pointconv_kernel(const float* __restrict__ pos, const float* __restrict__ feat,
                      const float* __restrict__ W1, const float* __restrict__ b1)
{
    extern __shared__ uint32_t smw[];
    const uint32_t sb = smem_u32(smw);

    const int tid  = threadIdx.x;
    const int lane = tid & 31, warp = tid >> 5;
    const int wm = warp & 3, wn = warp >> 2;      // 4 M-warps, 4 N-warps
    const int g  = lane >> 2, tg = lane & 3;
    const int scene = blockIdx.x;

    // cp.async issue of feature slice q (chunk q>>3, k-slice q&7) into stage q%3
    auto issue = [&](int q) {
        const int st = q % 3;
        const float* base = feat + ((size_t)scene * PTS + (size_t)(q >> 3) * 128) * CIN + (q & 7) * 32;
        const uint32_t d0 = sb + (ST_W + st * 4608) * 4;
#pragma unroll
        for (int j = 0; j < 2; j++) {
            int ch = tid + 512 * j;               // 0..1023 chunks of 16B
            int row = ch >> 3, c = ch & 7;
            CP16(d0 + (uint32_t)(row * 144 + c * 16), base + (size_t)row * CIN + c * 4);
        }
        CPC();
    };

    // fp32 stage -> fp16 perm operand buffer (one slice)
    auto convert = [&](int q) {
        const int st = q % 3, bf = q & 1;
        const int row = tid >> 2, seg = tid & 3;
        const float4* sp4 = (const float4*)(smw + ST_W + st * 4608 + row * 36 + seg * 8);
        float4 f0 = sp4[0], f1 = sp4[1];
        half2* dst = (half2*)(smw + FB_W + bf * 3072 + row * 24 + (seg >> 1) * 8 + (seg & 1));
        dst[0] = __floats2half2_rn(f0.x, f0.y);
        dst[2] = __floats2half2_rn(f0.z, f0.w);
        dst[4] = __floats2half2_rn(f1.x, f1.y);
        dst[6] = __floats2half2_rn(f1.z, f1.w);
    };

    // ---- prologue ----
    issue(0); issue(1); issue(2);

    // zero tail-A and tail-B block (rarely-written positions stay 0)
    for (int i = tid; i < 1024; i += 512) smw[TL_W + i] = 0;
    for (int i = tid; i < 2048; i += 512) smw[BH_W + 16 * 2048 + i] = 0;

    // centroid partials -> warp shuffle -> red
    {
        float sx = 0.f, sy = 0.f, sz = 0.f;
        const float* p = pos + (size_t)scene * PTS * 3;
        for (int i = tid; i < PTS; i += 512) {
            sx += p[i * 3 + 0]; sy += p[i * 3 + 1]; sz += p[i * 3 + 2];
        }
#pragma unroll
        for (int off = 16; off > 0; off >>= 1) {
            sx += __shfl_xor_sync(0xffffffffu, sx, off);
            sy += __shfl_xor_sync(0xffffffffu, sy, off);
            sz += __shfl_xor_sync(0xffffffffu, sz, off);
        }
        float* red = (float*)(smw + RED_W);
        if (lane == 0) { red[warp] = sx; red[32 + warp] = sy; red[64 + warp] = sz; }
    }
    __syncthreads();
    if (tid < 3) {
        const float* red = (const float*)(smw + RED_W);
        float s = 0.f;
        for (int w = 0; w < 16; w++) s += red[tid * 32 + w];
        ((float*)(smw + CEN_W))[tid] = s * (1.f / PTS);
    }
    // stage W1 -> fp16 perm layout (includes tail rows 256..258 into block 16)
    for (int idx = tid; idx < 259 * 256; idx += 512) {
        int k = idx >> 8, n = idx & 255;
        float v = W1[(size_t)k * 256 + n];
        int kb = k >> 4, kk = k & 15;
        int p_ = ((kk & 7) >> 1) * 4 + ((kk >> 3) & 1) * 2 + (kk & 1);
        ((__half*)(smw + BH_W))[kb * 4096 + n * 16 + p_] = __float2half(v);
    }
    CPW(2);
    __syncthreads();
    convert(0);

    const float cx = ((float*)(smw + CEN_W))[0];
    const float cy = ((float*)(smw + CEN_W))[1];
    const float cz = ((float*)(smw + CEN_W))[2];

    float acc[2][8][4], rmax[8][2];
#pragma unroll
    for (int ni = 0; ni < 8; ni++) { rmax[ni][0] = -FLT_MAX; rmax[ni][1] = -FLT_MAX; }

    // ---- main loop: 128 slices (16 chunks x 8) ----
    for (int i = 0; i < 128; i++) {
        CPW(1);
        __syncthreads();
        if (i + 3 < 128) issue(i + 3);
        if (i + 1 < 128) convert(i + 1);

        if ((i & 7) == 0) {
#pragma unroll
            for (int mi = 0; mi < 2; mi++)
#pragma unroll
                for (int ni = 0; ni < 8; ni++)
#pragma unroll
                    for (int j = 0; j < 4; j++) acc[mi][ni][j] = 0.f;
            if (tid < 128) {   // rel-pos for this chunk into tail buffer
                const int gr = scene * PTS + (i >> 3) * 128 + tid;
                ((half2*)(smw + TL_W + tid * 8))[0] =
                    __floats2half2_rn(pos[gr * 3 + 0] - cx, pos[gr * 3 + 1] - cy);
                ((half2*)(smw + TL_W + tid * 8 + 2))[0] =
                    __floats2half2_rn(pos[gr * 3 + 2] - cz, 0.f);
            }
        }

        // mma over this 32k slice (2 k16 steps)
        const uint32_t* fb = smw + FB_W + (i & 1) * 3072;
#pragma unroll
        for (int step = 0; step < 2; step++) {
            uint32_t a[2][4];
#pragma unroll
            for (int mi = 0; mi < 2; mi++) {
                const int R = wm * 32 + mi * 16 + g;
                uint2 x = *(const uint2*)(fb + R * 24 + step * 8 + 2 * tg);
                uint2 y = *(const uint2*)(fb + (R + 8) * 24 + step * 8 + 2 * tg);
                a[mi][0] = x.x; a[mi][1] = y.x; a[mi][2] = x.y; a[mi][3] = y.y;
            }
            const uint32_t* bh = smw + BH_W + ((i & 7) * 2 + step) * 2048;
#pragma unroll
            for (int ni = 0; ni < 8; ni++) {
                uint2 b = *(const uint2*)(bh + (wn * 64 + ni * 8 + g) * 8 + 2 * tg);
                MMA16(acc[0][ni], a[0], b);
                MMA16(acc[1][ni], a[1], b);
            }
        }

        if ((i & 7) == 7) {
            // tail k16 step: rel-pos
            uint32_t a[2][4];
#pragma unroll
            for (int mi = 0; mi < 2; mi++) {
                const int R = wm * 32 + mi * 16 + g;
                uint2 x = *(const uint2*)(smw + TL_W + R * 8 + 2 * tg);
                uint2 y = *(const uint2*)(smw + TL_W + (R + 8) * 8 + 2 * tg);
                a[mi][0] = x.x; a[mi][1] = y.x; a[mi][2] = x.y; a[mi][3] = y.y;
            }
            const uint32_t* bh = smw + BH_W + 16 * 2048;
#pragma unroll
            for (int ni = 0; ni < 8; ni++) {
                uint2 b = *(const uint2*)(bh + (wn * 64 + ni * 8 + g) * 8 + 2 * tg);
                MMA16(acc[0][ni], a[0], b);
                MMA16(acc[1][ni], a[1], b);
            }
            // fold into running max (bias/relu deferred: max commutes with +b, relu)
#pragma unroll
            for (int ni = 0; ni < 8; ni++)
#pragma unroll
                for (int p = 0; p < 2; p++)
                    rmax[ni][p] = fmaxf(rmax[ni][p],
                        fmaxf(fmaxf(acc[0][ni][p], acc[0][ni][p + 2]),
                              fmaxf(acc[1][ni][p], acc[1][ni][p + 2])));
        }
    }

    // ---- reduce rows: shuffle over g, combine 4 wm warps in smem ----
#pragma unroll
    for (int off = 4; off < 32; off <<= 1)
#pragma unroll
        for (int ni = 0; ni < 8; ni++)
#pragma unroll
            for (int p = 0; p < 2; p++)
                rmax[ni][p] = fmaxf(rmax[ni][p], __shfl_xor_sync(0xffffffffu, rmax[ni][p], off));

    __syncthreads();
    float* red = (float*)(smw + RED_W);
    if (lane < 4) {
#pragma unroll
        for (int ni = 0; ni < 8; ni++)
#pragma unroll
            for (int p = 0; p < 2; p++)
                red[wm * 256 + wn * 64 + ni * 8 + 2 * tg + p] = rmax[ni][p];
    }
    __syncthreads();
    if (tid < 256) {
        float v = fmaxf(fmaxf(red[tid], red[256 + tid]),
                        fmaxf(red[512 + tid], red[768 + tid]));
        v = fmaxf(v + b1[tid], 0.f);
        g_agg[scene * 256 + tid] = v;
    }
}

// ==================== head: GEMM2 + softplus + rsample ====================
// grid (2 col-blocks of 128, 16 scene-blocks of 8); each thread: 1 col x 4 scenes, mu+sigma.
__global__ __launch_bounds__(256, 1)
void head_kernel(const float* __restrict__ W2, const float* __restrict__ b2,
                 const float* __restrict__ noise, float* __restrict__ out) {
    const int t = threadIdx.x;
    const int col = blockIdx.x * 128 + (t & 127);
    const int sg  = (t >> 7) * 4;
    const int sbase = blockIdx.y * 8;
    __shared__ float ag[256 * 8];
#pragma unroll
    for (int i = 0; i < 8; i++) ag[t * 8 + i] = g_agg[(sbase + i) * 256 + t];
    __syncthreads();

    float amu[4] = {0.f, 0.f, 0.f, 0.f}, asg[4] = {0.f, 0.f, 0.f, 0.f};
#pragma unroll 4
    for (int k = 0; k < 256; k++) {
        const float wmu = W2[(size_t)k * 512 + col];
        const float wsg = W2[(size_t)k * 512 + col + 256];
        const float4 av = *(const float4*)&ag[k * 8 + sg];
        amu[0] = fmaf(av.x, wmu, amu[0]); asg[0] = fmaf(av.x, wsg, asg[0]);
        amu[1] = fmaf(av.y, wmu, amu[1]); asg[1] = fmaf(av.y, wsg, asg[1]);
        amu[2] = fmaf(av.z, wmu, amu[2]); asg[2] = fmaf(av.z, wsg, asg[2]);
        amu[3] = fmaf(av.w, wmu, amu[3]); asg[3] = fmaf(av.w, wsg, asg[3]);
    }
    const float bmu = b2[col], bsg = b2[col + 256];
#pragma unroll
    for (int j = 0; j < 4; j++) {
        const int s = sbase + sg + j;
        float mu = amu[j] + bmu;
        float sr = asg[j] + bsg;
        float sp = fmaxf(sr, 0.f) + log1pf(expf(-fabsf(sr)));
        out[s * 256 + col] = mu + (sp + 1e-4f) * noise[s * 256 + col];
    }
}

extern "C" void kernel_launch(void* const* d_in, const int* in_sizes, int n_in,
                              void* d_out, int out_size) {
    const float* pos     = (const float*)d_in[0];
    const float* feature = (const float*)d_in[1];
    // d_in[2] = batch: structurally i >> 11, never read
    const float* W1      = (const float*)d_in[3];
    const float* b1      = (const float*)d_in[4];
    const float* W2      = (const float*)d_in[5];
    const float* b2      = (const float*)d_in[6];
    const float* noise   = (const float*)d_in[7];
    float* out = (float*)d_out;

    cudaFuncSetAttribute(pointconv_kernel,
                         cudaFuncAttributeMaxDynamicSharedMemorySize, SMEM_BYTES);

    pointconv_kernel<<<NB, 512, SMEM_BYTES>>>(pos, feature, W1, b1);
    head_kernel<<<dim3(2, 16), 256>>>(W2, b2, noise, out);
}

// round 7
// speedup vs baseline: 1.1338x; 1.1338x over previous
#include <cuda_runtime.h>
#include <cuda_fp16.h>
#include <cstdint>
#include <cfloat>

#define NB  128
#define PTS 2048
#define CIN 256
#define NITEMS 1024                   // 128 scenes * 8 chunks of 256 pts

// ---- smem word (uint32) offsets ----
#define BH_W   0                      // W1 fp16: 17 k16-blocks * 256 n * 8 words
#define FB_W   34816                  // A fp16 operand, 2 bufs * 128 rows * 24 words
#define TL_W   40960                  // tail A fp16: 128 rows * 8 words
#define ST_W   41984                  // fp32 stage ring: 3 * 128 rows * 36 words
#define RED_W  55808                  // 1024 floats
#define SMEM_WORDS 56832
#define SMEM_BYTES (SMEM_WORDS * 4)   // 227328 B

#define ENC_NEG 0x00800000u           // encode(-FLT_MAX)

__device__ unsigned g_agg_u[NB * 256];
__device__ float    g_center[NB * 4];

__device__ __forceinline__ unsigned encf(float f) {
    unsigned u = __float_as_uint(f);
    return u ^ (((int)u >> 31) | 0x80000000u);
}
__device__ __forceinline__ float decf(unsigned u) {
    return __uint_as_float((u & 0x80000000u) ? (u ^ 0x80000000u) : ~u);
}
__device__ __forceinline__ uint32_t smem_u32(const void* p) {
    uint32_t a;
    asm("{ .reg .u64 t; cvta.to.shared.u64 t, %1; cvt.u32.u64 %0, t; }" : "=r"(a) : "l"(p));
    return a;
}
#define CP16(dst, src) asm volatile("cp.async.cg.shared.global [%0], [%1], 16;" :: "r"(dst), "l"(src) : "memory")
#define CPC()   asm volatile("cp.async.commit_group;" ::: "memory")
#define CPW(n)  asm volatile("cp.async.wait_group %0;" :: "n"(n) : "memory")

#define MMA16(c, a, b)                                                          \
    asm volatile("mma.sync.aligned.m16n8k16.row.col.f32.f16.f16.f32 "           \
        "{%0,%1,%2,%3}, {%4,%5,%6,%7}, {%8,%9}, {%0,%1,%2,%3};\n"               \
        : "+f"((c)[0]), "+f"((c)[1]), "+f"((c)[2]), "+f"((c)[3])                \
        : "r"((a)[0]), "r"((a)[1]), "r"((a)[2]), "r"((a)[3]),                   \
          "r"((b).x), "r"((b).y))

// ==================== centroid + g_agg init ====================
__global__ __launch_bounds__(256, 4)
void centroid_kernel(const float* __restrict__ pos) {
    __shared__ float red[24];
    const int b = blockIdx.x, t = threadIdx.x, lane = t & 31, w = t >> 5;
    const float* p = pos + (size_t)b * PTS * 3;
    float sx = 0.f, sy = 0.f, sz = 0.f;
    for (int i = t; i < PTS; i += 256) {
        sx += p[i * 3 + 0]; sy += p[i * 3 + 1]; sz += p[i * 3 + 2];
    }
#pragma unroll
    for (int off = 16; off > 0; off >>= 1) {
        sx += __shfl_xor_sync(0xffffffffu, sx, off);
        sy += __shfl_xor_sync(0xffffffffu, sy, off);
        sz += __shfl_xor_sync(0xffffffffu, sz, off);
    }
    if (lane == 0) { red[w] = sx; red[8 + w] = sy; red[16 + w] = sz; }
    g_agg_u[b * 256 + t] = ENC_NEG;          // init seg-max targets (t covers 0..255)
    __syncthreads();
    if (t < 3) {
        float s = 0.f;
        for (int i = 0; i < 8; i++) s += red[t * 8 + i];
        g_center[b * 4 + t] = s * (1.f / PTS);
    }
}

// ==================== persistent pointconv: GEMM1(fp16 mma) + seg-max(atomic) ====================
// grid = nCTA (one per SM). Items (scene, 256-pt chunk) assigned round-robin.
// Per item: 2 row-blocks of 128; per block: 8 k32 feature slices + rel-pos tail.
__global__ __launch_bounds__(512, 1)
void pointconv_kernel(const float* __restrict__ pos, const float* __restrict__ feat,
                      const float* __restrict__ W1, int nCTA)
{
    extern __shared__ uint32_t smw[];
    const uint32_t sb = smem_u32(smw);

    const int tid  = threadIdx.x;
    const int lane = tid & 31, warp = tid >> 5;
    const int wm = warp & 3, wn = warp >> 2;
    const int g  = lane >> 2, tg = lane & 3;
    const int c  = blockIdx.x;

    const int n_items = (c < NITEMS) ? ((NITEMS - 1 - c) / nCTA + 1) : 0;
    const int TS = n_items * 16;

    // slice q -> feature gmem row base and k-slice
    auto issue = [&](int q) {
        if (q < TS) {
            const int item = c + (q >> 4) * nCTA, sub = q & 15;
            const int R = (item >> 3) * PTS + (item & 7) * 256 + ((sub >> 3) << 7);
            const float* base = feat + (size_t)R * CIN + (sub & 7) * 32;
            const uint32_t d0 = sb + (ST_W + (q % 3) * 4608) * 4;
#pragma unroll
            for (int j = 0; j < 2; j++) {
                int ch = tid + 512 * j;
                int row = ch >> 3, cc = ch & 7;
                CP16(d0 + (uint32_t)(row * 144 + cc * 16), base + (size_t)row * CIN + cc * 4);
            }
        }
        CPC();
    };
    auto convert = [&](int q) {
        const int st = q % 3, bf = q & 1;
        const int row = tid >> 2, seg = tid & 3;
        const float4* sp4 = (const float4*)(smw + ST_W + st * 4608 + row * 36 + seg * 8);
        float4 f0 = sp4[0], f1 = sp4[1];
        half2* dst = (half2*)(smw + FB_W + bf * 3072 + row * 24 + (seg >> 1) * 8 + (seg & 1));
        dst[0] = __floats2half2_rn(f0.x, f0.y);
        dst[2] = __floats2half2_rn(f0.z, f0.w);
        dst[4] = __floats2half2_rn(f1.x, f1.y);
        dst[6] = __floats2half2_rn(f1.z, f1.w);
    };

    // ---- prologue ----
    issue(0); issue(1); issue(2);
    for (int i = tid; i < 1024; i += 512) smw[TL_W + i] = 0;
    for (int i = tid; i < 2048; i += 512) smw[BH_W + 16 * 2048 + i] = 0;
    // stage W1 -> fp16 perm layout (k perm: (k,k+1,k+8,k+9) contiguous)
    for (int idx = tid; idx < 259 * 256; idx += 512) {
        int k = idx >> 8, n = idx & 255;
        float v = W1[(size_t)k * 256 + n];
        int kb = k >> 4, kk = k & 15;
        int p_ = ((kk & 7) >> 1) * 4 + ((kk >> 3) & 1) * 2 + (kk & 1);
        ((__half*)(smw + BH_W))[kb * 4096 + n * 16 + p_] = __float2half(v);
    }
    CPW(2);
    __syncthreads();
    if (TS > 0) convert(0);

    float acc[2][8][4], rmax[8][2];
#pragma unroll
    for (int ni = 0; ni < 8; ni++) { rmax[ni][0] = -FLT_MAX; rmax[ni][1] = -FLT_MAX; }

    for (int i = 0; i < TS; i++) {
        CPW(1);
        __syncthreads();
        issue(i + 3);
        if (i + 1 < TS) convert(i + 1);

        const int item = c + (i >> 4) * nCTA, sub = i & 15;
        const int Rb = (item >> 3) * PTS + (item & 7) * 256 + ((sub >> 3) << 7);

        if ((i & 7) == 0) {
#pragma unroll
            for (int mi = 0; mi < 2; mi++)
#pragma unroll
                for (int ni = 0; ni < 8; ni++)
#pragma unroll
                    for (int j = 0; j < 4; j++) acc[mi][ni][j] = 0.f;
            if (tid < 128) {   // rel-pos tail for this 128-row block
                const int sc = item >> 3;
                const float cx = g_center[sc * 4 + 0];
                const float cy = g_center[sc * 4 + 1];
                const float cz = g_center[sc * 4 + 2];
                const int gr = Rb + tid;
                ((half2*)(smw + TL_W + tid * 8))[0] =
                    __floats2half2_rn(pos[gr * 3 + 0] - cx, pos[gr * 3 + 1] - cy);
                ((half2*)(smw + TL_W + tid * 8 + 2))[0] =
                    __floats2half2_rn(pos[gr * 3 + 2] - cz, 0.f);
            }
        }

        // mma over this k32 slice (2 k16 steps)
        const uint32_t* fb = smw + FB_W + (i & 1) * 3072;
#pragma unroll
        for (int step = 0; step < 2; step++) {
            uint32_t a[2][4];
#pragma unroll
            for (int mi = 0; mi < 2; mi++) {
                const int R = wm * 32 + mi * 16 + g;
                uint2 x = *(const uint2*)(fb + R * 24 + step * 8 + 2 * tg);
                uint2 y = *(const uint2*)(fb + (R + 8) * 24 + step * 8 + 2 * tg);
                a[mi][0] = x.x; a[mi][1] = y.x; a[mi][2] = x.y; a[mi][3] = y.y;
            }
            const uint32_t* bh = smw + BH_W + ((i & 7) * 2 + step) * 2048;
#pragma unroll
            for (int ni = 0; ni < 8; ni++) {
                uint2 b = *(const uint2*)(bh + (wn * 64 + ni * 8 + g) * 8 + 2 * tg);
                MMA16(acc[0][ni], a[0], b);
                MMA16(acc[1][ni], a[1], b);
            }
        }

        if ((i & 7) == 7) {
            // tail k16 step (rel-pos) + fold into running max
            uint32_t a[2][4];
#pragma unroll
            for (int mi = 0; mi < 2; mi++) {
                const int R = wm * 32 + mi * 16 + g;
                uint2 x = *(const uint2*)(smw + TL_W + R * 8 + 2 * tg);
                uint2 y = *(const uint2*)(smw + TL_W + (R + 8) * 8 + 2 * tg);
                a[mi][0] = x.x; a[mi][1] = y.x; a[mi][2] = x.y; a[mi][3] = y.y;
            }
            const uint32_t* bh = smw + BH_W + 16 * 2048;
#pragma unroll
            for (int ni = 0; ni < 8; ni++) {
                uint2 b = *(const uint2*)(bh + (wn * 64 + ni * 8 + g) * 8 + 2 * tg);
                MMA16(acc[0][ni], a[0], b);
                MMA16(acc[1][ni], a[1], b);
            }
#pragma unroll
            for (int ni = 0; ni < 8; ni++)
#pragma unroll
                for (int p = 0; p < 2; p++)
                    rmax[ni][p] = fmaxf(rmax[ni][p],
                        fmaxf(fmaxf(acc[0][ni][p], acc[0][ni][p + 2]),
                              fmaxf(acc[1][ni][p], acc[1][ni][p + 2])));
        }

        if ((i & 15) == 15) {
            // item finished: reduce 256-col max and publish via atomicMax
#pragma unroll
            for (int off = 4; off < 32; off <<= 1)
#pragma unroll
                for (int ni = 0; ni < 8; ni++)
#pragma unroll
                    for (int p = 0; p < 2; p++)
                        rmax[ni][p] = fmaxf(rmax[ni][p],
                                            __shfl_xor_sync(0xffffffffu, rmax[ni][p], off));
            float* red = (float*)(smw + RED_W);
            if (lane < 4) {
#pragma unroll
                for (int ni = 0; ni < 8; ni++)
#pragma unroll
                    for (int p = 0; p < 2; p++)
                        red[wm * 256 + wn * 64 + ni * 8 + 2 * tg + p] = rmax[ni][p];
            }
            __syncthreads();
            if (tid < 256) {
                float v = fmaxf(fmaxf(red[tid], red[256 + tid]),
                                fmaxf(red[512 + tid], red[768 + tid]));
                atomicMax(&g_agg_u[(item >> 3) * 256 + tid], encf(v));
            }
#pragma unroll
            for (int ni = 0; ni < 8; ni++) { rmax[ni][0] = -FLT_MAX; rmax[ni][1] = -FLT_MAX; }
        }
    }
}

// ==================== head: decode + bias/relu + GEMM2 + softplus + rsample ====================
// grid (2 col-halves, 32 scene-quads); 512 threads: col = t&127 (+128*blockIdx.x), scene = t>>7.
__global__ __launch_bounds__(512, 2)
void head_kernel(const float* __restrict__ b1, const float* __restrict__ W2,
                 const float* __restrict__ b2, const float* __restrict__ noise,
                 float* __restrict__ out) {
    const int t = threadIdx.x;
    const int sbase = blockIdx.y * 4;
    __shared__ float ag[4 * 256];
#pragma unroll
    for (int j = 0; j < 2; j++) {
        int e = t + 512 * j;                    // 0..1023
        int sl = e >> 8, k = e & 255;
        float f = decf(g_agg_u[(sbase + sl) * 256 + k]);
        ag[sl * 256 + k] = fmaxf(f + b1[k], 0.f);
    }
    __syncthreads();

    const int col = blockIdx.x * 128 + (t & 127);
    const int sl  = t >> 7;
    const float* a = ag + sl * 256;
    float amu = 0.f, asg = 0.f;
#pragma unroll 8
    for (int k = 0; k < 256; k++) {
        const float av = a[k];
        amu = fmaf(av, W2[(size_t)k * 512 + col], amu);
        asg = fmaf(av, W2[(size_t)k * 512 + col + 256], asg);
    }
    const int s = sbase + sl;
    float mu = amu + b2[col];
    float sr = asg + b2[col + 256];
    float sp = fmaxf(sr, 0.f) + log1pf(expf(-fabsf(sr)));
    out[s * 256 + col] = mu + (sp + 1e-4f) * noise[s * 256 + col];
}

extern "C" void kernel_launch(void* const* d_in, const int* in_sizes, int n_in,
                              void* d_out, int out_size) {
    const float* pos     = (const float*)d_in[0];
    const float* feature = (const float*)d_in[1];
    // d_in[2] = batch: structurally i >> 11, never read
    const float* W1      = (const float*)d_in[3];
    const float* b1      = (const float*)d_in[4];
    const float* W2      = (const float*)d_in[5];
    const float* b2      = (const float*)d_in[6];
    const float* noise   = (const float*)d_in[7];
    float* out = (float*)d_out;

    int nsm = 148;
    if (cudaDeviceGetAttribute(&nsm, cudaDevAttrMultiProcessorCount, 0) != cudaSuccess || nsm < 1)
        nsm = 148;
    if (nsm > NITEMS) nsm = NITEMS;

    cudaFuncSetAttribute(pointconv_kernel,
                         cudaFuncAttributeMaxDynamicSharedMemorySize, SMEM_BYTES);

    centroid_kernel<<<NB, 256>>>(pos);
    pointconv_kernel<<<nsm, 512, SMEM_BYTES>>>(pos, feature, W1, nsm);
    head_kernel<<<dim3(2, 32), 512>>>(b1, W2, b2, noise, out);
}

// round 9
// speedup vs baseline: 1.2356x; 1.0898x over previous
#include <cuda_runtime.h>
#include <cuda_fp16.h>
#include <cstdint>
#include <cfloat>

#define NB  128
#define PTS 2048
#define CIN 256
#define NITEMS 1024                   // 128 scenes * 8 chunks of 256 pts

// ---- smem word (uint32) offsets ----
#define BH_W   0                      // W1 fp16: 17 k16-blocks * 256 n * 8 words
#define FB_W   34816                  // A fp16 operand, 2 bufs * 128 rows * 24 words
#define TL_W   40960                  // tail A fp16: 128 rows * 8 words
#define ST_W   41984                  // fp32 stage ring: 3 * 128 rows * 36 words
#define RED_W  55808                  // 1024 floats
#define SMEM_WORDS 56832
#define SMEM_BYTES (SMEM_WORDS * 4)   // 227328 B

#define ENC_NEG 0x00800000u           // encode(-FLT_MAX)

__device__ unsigned g_agg_u[NB * 256];
__device__ uint32_t g_w1h[17 * 2048]; // W1 fp16 perm layout (17 k16-blocks * 256n * 8 words)

__device__ __forceinline__ unsigned encf(float f) {
    unsigned u = __float_as_uint(f);
    return u ^ (((int)u >> 31) | 0x80000000u);
}
__device__ __forceinline__ float decf(unsigned u) {
    return __uint_as_float((u & 0x80000000u) ? (u ^ 0x80000000u) : ~u);
}
__device__ __forceinline__ uint32_t smem_u32(const void* p) {
    uint32_t a;
    asm("{ .reg .u64 t; cvta.to.shared.u64 t, %1; cvt.u32.u64 %0, t; }" : "=r"(a) : "l"(p));
    return a;
}
#define CP16(dst, src) asm volatile("cp.async.cg.shared.global [%0], [%1], 16;" :: "r"(dst), "l"(src) : "memory")
#define CPC()   asm volatile("cp.async.commit_group;" ::: "memory")
#define CPW(n)  asm volatile("cp.async.wait_group %0;" :: "n"(n) : "memory")

#define MMA16(c, a, b)                                                          \
    asm volatile("mma.sync.aligned.m16n8k16.row.col.f32.f16.f16.f32 "           \
        "{%0,%1,%2,%3}, {%4,%5,%6,%7}, {%8,%9}, {%0,%1,%2,%3};\n"               \
        : "+f"((c)[0]), "+f"((c)[1]), "+f"((c)[2]), "+f"((c)[3])                \
        : "r"((a)[0]), "r"((a)[1]), "r"((a)[2]), "r"((a)[3]),                   \
          "r"((b).x), "r"((b).y))

// ==================== prep: W1 -> fp16 perm layout in gmem + agg init ====================
__global__ __launch_bounds__(256, 8)
void prep_kernel(const float* __restrict__ W1) {
    const int bid = blockIdx.x, t = threadIdx.x;
    if (bid < 136) {
        const int d = bid * 256 + t;             // word index 0..34815
        const int kb = d >> 11, rem = d & 2047;
        const int n = rem >> 3, wp = rem & 7;
        const int kk0 = (wp & 1) ? (wp + 7) : wp;     // word->k mapping (verified vs perm)
        const int k0 = kb * 16 + kk0, k1 = k0 + 1;
        const float v0 = (k0 < 259) ? W1[(size_t)k0 * 256 + n] : 0.f;
        const float v1 = (k1 < 259) ? W1[(size_t)k1 * 256 + n] : 0.f;
        half2 h = __floats2half2_rn(v0, v1);
        g_w1h[d] = *(const uint32_t*)&h;
    } else {
        const int e = (bid - 136) * 1024 + t;
#pragma unroll
        for (int j = 0; j < 4; j++) g_agg_u[e + 256 * j] = ENC_NEG;
    }
}

// ==================== persistent pointconv: GEMM1(fp16 mma) + seg-max(atomic) ====================
// Centroid-free: tail rows use RAW pos; per-scene constant (b1 - c@W1b) applied in head.
__global__ __launch_bounds__(512, 1)
void pointconv_kernel(const float* __restrict__ pos, const float* __restrict__ feat, int nCTA)
{
    extern __shared__ uint32_t smw[];
    const uint32_t sb = smem_u32(smw);

    const int tid  = threadIdx.x;
    const int lane = tid & 31, warp = tid >> 5;
    const int wm = warp & 3, wn = warp >> 2;
    const int g  = lane >> 2, tg = lane & 3;
    const int c  = blockIdx.x;

    const int n_items = (c < NITEMS) ? ((NITEMS - 1 - c) / nCTA + 1) : 0;
    const int TS = n_items * 16;

    auto issue = [&](int q) {
        if (q < TS) {
            const int item = c + (q >> 4) * nCTA, sub = q & 15;
            const int R = (item >> 3) * PTS + (item & 7) * 256 + ((sub >> 3) << 7);
            const float* base = feat + (size_t)R * CIN + (sub & 7) * 32;
            const uint32_t d0 = sb + (ST_W + (q % 3) * 4608) * 4;
#pragma unroll
            for (int j = 0; j < 2; j++) {
                int ch = tid + 512 * j;
                int row = ch >> 3, cc = ch & 7;
                CP16(d0 + (uint32_t)(row * 144 + cc * 16), base + (size_t)row * CIN + cc * 4);
            }
        }
        CPC();
    };
    // fp32 stage -> fp16 perm operand: thread (row, part): 2 LDS.128 + 1 STS.128
    auto convert = [&](int q) {
        const int st = q % 3, bf = q & 1;
        const int row = tid >> 2, p = tid & 3;
        const int step = p >> 1, sub = p & 1;
        const float* s0 = (const float*)(smw + ST_W + st * 4608 + row * 36 + step * 16 + sub * 4);
        const float4 fA = *(const float4*)s0;
        const float4 fB = *(const float4*)(s0 + 8);
        half2 w0 = __floats2half2_rn(fA.x, fA.y);
        half2 w1 = __floats2half2_rn(fB.x, fB.y);
        half2 w2 = __floats2half2_rn(fA.z, fA.w);
        half2 w3 = __floats2half2_rn(fB.z, fB.w);
        uint4 v = make_uint4(*(uint32_t*)&w0, *(uint32_t*)&w1, *(uint32_t*)&w2, *(uint32_t*)&w3);
        *(uint4*)(smw + FB_W + bf * 3072 + row * 24 + step * 8 + sub * 4) = v;
    };

    // ---- prologue: W1 via cp.async + first 3 feature slices ----
    {
        const uint32_t dW = sb + BH_W * 4;
#pragma unroll
        for (int j = 0; j < 17; j++) {
            int w = (tid + 512 * j) * 4;          // word offset, 4 words per chunk
            CP16(dW + (uint32_t)w * 4, g_w1h + w);
        }
        CPC();
    }
    issue(0); issue(1); issue(2);
    CPW(2);                                        // W1 + slice0 landed
    __syncthreads();
    if (TS > 0) convert(0);

    float acc[2][8][4], rmax[8][2];
#pragma unroll
    for (int ni = 0; ni < 8; ni++) { rmax[ni][0] = -FLT_MAX; rmax[ni][1] = -FLT_MAX; }

    for (int i = 0; i < TS; i++) {
        CPW(1);
        __syncthreads();
        issue(i + 3);
        if (i + 1 < TS) convert(i + 1);

        const int item = c + (i >> 4) * nCTA, sub = i & 15;
        const int Rb = (item >> 3) * PTS + (item & 7) * 256 + ((sub >> 3) << 7);

        if ((i & 7) == 0) {
#pragma unroll
            for (int mi = 0; mi < 2; mi++)
#pragma unroll
                for (int ni = 0; ni < 8; ni++)
#pragma unroll
                    for (int j = 0; j < 4; j++) acc[mi][ni][j] = 0.f;
            if (tid < 128) {   // raw-pos tail rows; z (kk=2) lives in WORD 2 per perm layout
                const int gr = Rb + tid;
                half2 h0 = __floats2half2_rn(pos[gr * 3 + 0], pos[gr * 3 + 1]);
                half2 h1 = __floats2half2_rn(pos[gr * 3 + 2], 0.f);
                *(uint4*)(smw + TL_W + tid * 8) =
                    make_uint4(*(uint32_t*)&h0, 0u, *(uint32_t*)&h1, 0u);
                *(uint4*)(smw + TL_W + tid * 8 + 4) = make_uint4(0u, 0u, 0u, 0u);
            }
        }

        const uint32_t* fb = smw + FB_W + (i & 1) * 3072;
#pragma unroll
        for (int step = 0; step < 2; step++) {
            uint32_t a[2][4];
#pragma unroll
            for (int mi = 0; mi < 2; mi++) {
                const int R = wm * 32 + mi * 16 + g;
                uint2 x = *(const uint2*)(fb + R * 24 + step * 8 + 2 * tg);
                uint2 y = *(const uint2*)(fb + (R + 8) * 24 + step * 8 + 2 * tg);
                a[mi][0] = x.x; a[mi][1] = y.x; a[mi][2] = x.y; a[mi][3] = y.y;
            }
            const uint32_t* bh = smw + BH_W + ((i & 7) * 2 + step) * 2048;
#pragma unroll
            for (int ni = 0; ni < 8; ni++) {
                uint2 b = *(const uint2*)(bh + (wn * 64 + ni * 8 + g) * 8 + 2 * tg);
                MMA16(acc[0][ni], a[0], b);
                MMA16(acc[1][ni], a[1], b);
            }
        }

        if ((i & 7) == 7) {
            // tail k16 (raw pos) + fold into running max
            uint32_t a[2][4];
#pragma unroll
            for (int mi = 0; mi < 2; mi++) {
                const int R = wm * 32 + mi * 16 + g;
                uint2 x = *(const uint2*)(smw + TL_W + R * 8 + 2 * tg);
                uint2 y = *(const uint2*)(smw + TL_W + (R + 8) * 8 + 2 * tg);
                a[mi][0] = x.x; a[mi][1] = y.x; a[mi][2] = x.y; a[mi][3] = y.y;
            }
            const uint32_t* bh = smw + BH_W + 16 * 2048;
#pragma unroll
            for (int ni = 0; ni < 8; ni++) {
                uint2 b = *(const uint2*)(bh + (wn * 64 + ni * 8 + g) * 8 + 2 * tg);
                MMA16(acc[0][ni], a[0], b);
                MMA16(acc[1][ni], a[1], b);
            }
#pragma unroll
            for (int ni = 0; ni < 8; ni++)
#pragma unroll
                for (int p = 0; p < 2; p++)
                    rmax[ni][p] = fmaxf(rmax[ni][p],
                        fmaxf(fmaxf(acc[0][ni][p], acc[0][ni][p + 2]),
                              fmaxf(acc[1][ni][p], acc[1][ni][p + 2])));
        }

        if ((i & 15) == 15) {
#pragma unroll
            for (int off = 4; off < 32; off <<= 1)
#pragma unroll
                for (int ni = 0; ni < 8; ni++)
#pragma unroll
                    for (int p = 0; p < 2; p++)
                        rmax[ni][p] = fmaxf(rmax[ni][p],
                                            __shfl_xor_sync(0xffffffffu, rmax[ni][p], off));
            float* red = (float*)(smw + RED_W);
            if (lane < 4) {
#pragma unroll
                for (int ni = 0; ni < 8; ni++)
#pragma unroll
                    for (int p = 0; p < 2; p++)
                        red[wm * 256 + wn * 64 + ni * 8 + 2 * tg + p] = rmax[ni][p];
            }
            __syncthreads();
            if (tid < 256) {
                float v = fmaxf(fmaxf(red[tid], red[256 + tid]),
                                fmaxf(red[512 + tid], red[768 + tid]));
                atomicMax(&g_agg_u[(item >> 3) * 256 + tid], encf(v));
            }
#pragma unroll
            for (int ni = 0; ni < 8; ni++) { rmax[ni][0] = -FLT_MAX; rmax[ni][1] = -FLT_MAX; }
        }
    }
}

// ==================== head: centroid + decode + (b1 - c@W1b) + relu + GEMM2 + sample ====================
__global__ __launch_bounds__(512, 2)
void head_kernel(const float* __restrict__ pos, const float* __restrict__ W1,
                 const float* __restrict__ b1, const float* __restrict__ W2,
                 const float* __restrict__ b2, const float* __restrict__ noise,
                 float* __restrict__ out) {
    const int t = threadIdx.x;
    const int sbase = blockIdx.y * 4;
    __shared__ float ag[4 * 256];
    __shared__ float cw[4][4][3];

    // centroid: 128 threads/scene, 16 pts (48 contiguous floats) each
    {
        const int sl = t >> 7, lt = t & 127;
        const float* p = pos + ((size_t)(sbase + sl) * PTS + (size_t)lt * 16) * 3;
        float s0 = 0.f, s1 = 0.f, s2 = 0.f;
#pragma unroll
        for (int j = 0; j < 12; j++) {
            const float4 f = *(const float4*)(p + j * 4);
            const int m = (4 * j) % 3;
            if (m == 0)      { s0 += f.x + f.w; s1 += f.y; s2 += f.z; }
            else if (m == 1) { s1 += f.x + f.w; s2 += f.y; s0 += f.z; }
            else             { s2 += f.x + f.w; s0 += f.y; s1 += f.z; }
        }
#pragma unroll
        for (int off = 16; off > 0; off >>= 1) {
            s0 += __shfl_xor_sync(0xffffffffu, s0, off);
            s1 += __shfl_xor_sync(0xffffffffu, s1, off);
            s2 += __shfl_xor_sync(0xffffffffu, s2, off);
        }
        if ((t & 31) == 0) {
            const int w = (t >> 5) & 3;
            cw[sl][w][0] = s0; cw[sl][w][1] = s1; cw[sl][w][2] = s2;
        }
    }
    __syncthreads();

    // decode seg-max, add (b1 - c@W1b), relu
#pragma unroll
    for (int jj = 0; jj < 2; jj++) {
        const int e = t + 512 * jj;
        const int sl = e >> 8, k = e & 255;
        const float cx = (cw[sl][0][0] + cw[sl][1][0] + cw[sl][2][0] + cw[sl][3][0]) * (1.f / PTS);
        const float cy = (cw[sl][0][1] + cw[sl][1][1] + cw[sl][2][1] + cw[sl][3][1]) * (1.f / PTS);
        const float cz = (cw[sl][0][2] + cw[sl][1][2] + cw[sl][2][2] + cw[sl][3][2]) * (1.f / PTS);
        const float dlt = b1[k] - (cx * W1[65536 + k] + cy * W1[65792 + k] + cz * W1[66048 + k]);
        const float f = decf(g_agg_u[(sbase + sl) * 256 + k]);
        ag[sl * 256 + k] = fmaxf(f + dlt, 0.f);
    }
    __syncthreads();

    const int col = blockIdx.x * 128 + (t & 127);
    const int sl  = t >> 7;
    const float* a = ag + sl * 256;
    float amu = 0.f, asg = 0.f;
#pragma unroll 8
    for (int k = 0; k < 256; k++) {
        const float av = a[k];
        amu = fmaf(av, W2[(size_t)k * 512 + col], amu);
        asg = fmaf(av, W2[(size_t)k * 512 + col + 256], asg);
    }
    const int s = sbase + sl;
    float mu = amu + b2[col];
    float sr = asg + b2[col + 256];
    float sp = fmaxf(sr, 0.f) + log1pf(expf(-fabsf(sr)));
    out[s * 256 + col] = mu + (sp + 1e-4f) * noise[s * 256 + col];
}

extern "C" void kernel_launch(void* const* d_in, const int* in_sizes, int n_in,
                              void* d_out, int out_size) {
    const float* pos     = (const float*)d_in[0];
    const float* feature = (const float*)d_in[1];
    // d_in[2] = batch: structurally i >> 11, never read
    const float* W1      = (const float*)d_in[3];
    const float* b1      = (const float*)d_in[4];
    const float* W2      = (const float*)d_in[5];
    const float* b2      = (const float*)d_in[6];
    const float* noise   = (const float*)d_in[7];
    float* out = (float*)d_out;

    int nsm = 148;
    if (cudaDeviceGetAttribute(&nsm, cudaDevAttrMultiProcessorCount, 0) != cudaSuccess || nsm < 1)
        nsm = 148;
    if (nsm > NITEMS) nsm = NITEMS;

    cudaFuncSetAttribute(pointconv_kernel,
                         cudaFuncAttributeMaxDynamicSharedMemorySize, SMEM_BYTES);

    prep_kernel<<<168, 256>>>(W1);
    pointconv_kernel<<<nsm, 512, SMEM_BYTES>>>(pos, feature, nsm);
    head_kernel<<<dim3(2, 32), 512>>>(pos, W1, b1, W2, b2, noise, out);
}

// round 10
// speedup vs baseline: 1.4323x; 1.1592x over previous
#include <cuda_runtime.h>
#include <cuda_fp16.h>
#include <cstdint>
#include <cfloat>

#define NB  128
#define PTS 2048
#define CIN 256
#define NITEMS 1024                   // 128 scenes * 8 chunks of 256 pts

// ---- smem word (uint32) offsets ----
#define BH_W   0                      // W1 fp16: 17 k16-blocks * 256 n * 8 words
#define FB_W   34816                  // A fp16 operand, 2 bufs * 128 rows * 24 words
#define TL_W   40960                  // tail A fp16: 128 rows * 8 words
#define RED_W  41984                  // 1024 floats
#define SMEM_WORDS 43008
#define SMEM_BYTES (SMEM_WORDS * 4)   // 172032 B

#define ENC_NEG 0x00800000u           // encode(-FLT_MAX)

__device__ unsigned g_agg_u[NB * 256];
__device__ uint32_t g_w1h[17 * 2048]; // W1 fp16 perm layout

__device__ __forceinline__ unsigned encf(float f) {
    unsigned u = __float_as_uint(f);
    return u ^ (((int)u >> 31) | 0x80000000u);
}
__device__ __forceinline__ float decf(unsigned u) {
    return __uint_as_float((u & 0x80000000u) ? (u ^ 0x80000000u) : ~u);
}
__device__ __forceinline__ uint32_t smem_u32(const void* p) {
    uint32_t a;
    asm("{ .reg .u64 t; cvta.to.shared.u64 t, %1; cvt.u32.u64 %0, t; }" : "=r"(a) : "l"(p));
    return a;
}
#define CP16(dst, src) asm volatile("cp.async.cg.shared.global [%0], [%1], 16;" :: "r"(dst), "l"(src) : "memory")
#define CPC()   asm volatile("cp.async.commit_group;" ::: "memory")
#define CPW(n)  asm volatile("cp.async.wait_group %0;" :: "n"(n) : "memory")

#define MMA16(c, a, b)                                                          \
    asm volatile("mma.sync.aligned.m16n8k16.row.col.f32.f16.f16.f32 "           \
        "{%0,%1,%2,%3}, {%4,%5,%6,%7}, {%8,%9}, {%0,%1,%2,%3};\n"               \
        : "+f"((c)[0]), "+f"((c)[1]), "+f"((c)[2]), "+f"((c)[3])                \
        : "r"((a)[0]), "r"((a)[1]), "r"((a)[2]), "r"((a)[3]),                   \
          "r"((b).x), "r"((b).y))

// ==================== prep: W1 -> fp16 perm layout in gmem + agg init ====================
__global__ __launch_bounds__(256, 8)
void prep_kernel(const float* __restrict__ W1) {
    const int bid = blockIdx.x, t = threadIdx.x;
    if (bid < 136) {
        const int d = bid * 256 + t;             // word index 0..34815
        const int kb = d >> 11, rem = d & 2047;
        const int n = rem >> 3, wp = rem & 7;
        const int kk0 = (wp & 1) ? (wp + 7) : wp;
        const int k0 = kb * 16 + kk0, k1 = k0 + 1;
        const float v0 = (k0 < 259) ? W1[(size_t)k0 * 256 + n] : 0.f;
        const float v1 = (k1 < 259) ? W1[(size_t)k1 * 256 + n] : 0.f;
        half2 h = __floats2half2_rn(v0, v1);
        g_w1h[d] = *(const uint32_t*)&h;
    } else {
        const int e = (bid - 136) * 1024 + t;
#pragma unroll
        for (int j = 0; j < 4; j++) g_agg_u[e + 256 * j] = ENC_NEG;
    }
}

// ==================== persistent pointconv: GEMM1(fp16 mma) + seg-max(atomic) ====================
// Direct gmem->reg->fp16-smem feed (no fp32 staging). Centroid-free tail (raw pos).
__global__ __launch_bounds__(512, 1)
void pointconv_kernel(const float* __restrict__ pos, const float* __restrict__ feat, int nCTA)
{
    extern __shared__ uint32_t smw[];
    const uint32_t sb = smem_u32(smw);

    const int tid  = threadIdx.x;
    const int lane = tid & 31, warp = tid >> 5;
    const int wm = warp & 3, wn = warp >> 2;
    const int g  = lane >> 2, tg = lane & 3;
    const int c  = blockIdx.x;

    const int n_items = (c < NITEMS) ? ((NITEMS - 1 - c) / nCTA + 1) : 0;
    const int TS = n_items * 16;

    // per-thread load coordinates: row = tid>>2, p = tid&3 -> (step, sub)
    const int lrow = tid >> 2, lp = tid & 3;
    const int lstep = lp >> 1, lsub = lp & 1;
    const int lkoff = lstep * 16 + lsub * 4;      // fp32 element offset inside 32-k slice

    // fetch slice q's fp32 for this thread into registers
    float4 bufA, bufB;
    auto fetch = [&](int q) {
        if (q < TS) {
            const int item = c + (q >> 4) * nCTA, sub = q & 15;
            const int R = (item >> 3) * PTS + (item & 7) * 256 + ((sub >> 3) << 7);
            const float* s0 = feat + (size_t)(R + lrow) * CIN + (sub & 7) * 32 + lkoff;
            bufA = *(const float4*)s0;
            bufB = *(const float4*)(s0 + 8);
        }
    };
    // convert registers (slice q) -> fp16 perm operand buffer fb[q&1]
    auto store_fb = [&](int q) {
        half2 w0 = __floats2half2_rn(bufA.x, bufA.y);
        half2 w1 = __floats2half2_rn(bufB.x, bufB.y);
        half2 w2 = __floats2half2_rn(bufA.z, bufA.w);
        half2 w3 = __floats2half2_rn(bufB.z, bufB.w);
        uint4 v = make_uint4(*(uint32_t*)&w0, *(uint32_t*)&w1, *(uint32_t*)&w2, *(uint32_t*)&w3);
        *(uint4*)(smw + FB_W + (q & 1) * 3072 + lrow * 24 + lstep * 8 + lsub * 4) = v;
    };

    // ---- prologue: W1 via cp.async; slice 0 direct to fb[0]; slice 1 into regs ----
    {
        const uint32_t dW = sb + BH_W * 4;
#pragma unroll
        for (int j = 0; j < 17; j++) {
            int w = (tid + 512 * j) * 4;
            CP16(dW + (uint32_t)w * 4, g_w1h + w);
        }
        CPC();
    }
    fetch(0);
    if (TS > 0) store_fb(0);
    fetch(1);
    CPW(0);                                        // W1 landed

    float acc[2][8][4], rmax[8][2];
#pragma unroll
    for (int ni = 0; ni < 8; ni++) { rmax[ni][0] = -FLT_MAX; rmax[ni][1] = -FLT_MAX; }

    for (int i = 0; i < TS; i++) {
        __syncthreads();                           // fb[(i+1)&1] consumers done; fb[i&1]/TL ready
        if (i + 1 < TS) store_fb(i + 1);           // regs -> fb[(i+1)&1]
        fetch(i + 2);                              // gmem -> regs (for next iter's store)

        const int item = c + (i >> 4) * nCTA, sub = i & 15;
        const int Rb = (item >> 3) * PTS + (item & 7) * 256 + ((sub >> 3) << 7);

        if ((i & 7) == 0) {
#pragma unroll
            for (int mi = 0; mi < 2; mi++)
#pragma unroll
                for (int ni = 0; ni < 8; ni++)
#pragma unroll
                    for (int j = 0; j < 4; j++) acc[mi][ni][j] = 0.f;
            if (tid < 128) {   // raw-pos tail rows; z (kk=2) lives in WORD 2 per perm layout
                const int gr = Rb + tid;
                half2 h0 = __floats2half2_rn(pos[gr * 3 + 0], pos[gr * 3 + 1]);
                half2 h1 = __floats2half2_rn(pos[gr * 3 + 2], 0.f);
                *(uint4*)(smw + TL_W + tid * 8) =
                    make_uint4(*(uint32_t*)&h0, 0u, *(uint32_t*)&h1, 0u);
                *(uint4*)(smw + TL_W + tid * 8 + 4) = make_uint4(0u, 0u, 0u, 0u);
            }
        }

        const uint32_t* fb = smw + FB_W + (i & 1) * 3072;
#pragma unroll
        for (int step = 0; step < 2; step++) {
            uint32_t a[2][4];
#pragma unroll
            for (int mi = 0; mi < 2; mi++) {
                const int R = wm * 32 + mi * 16 + g;
                uint2 x = *(const uint2*)(fb + R * 24 + step * 8 + 2 * tg);
                uint2 y = *(const uint2*)(fb + (R + 8) * 24 + step * 8 + 2 * tg);
                a[mi][0] = x.x; a[mi][1] = y.x; a[mi][2] = x.y; a[mi][3] = y.y;
            }
            const uint32_t* bh = smw + BH_W + ((i & 7) * 2 + step) * 2048;
#pragma unroll
            for (int ni = 0; ni < 8; ni++) {
                uint2 b = *(const uint2*)(bh + (wn * 64 + ni * 8 + g) * 8 + 2 * tg);
                MMA16(acc[0][ni], a[0], b);
                MMA16(acc[1][ni], a[1], b);
            }
        }

        if ((i & 7) == 7) {
            // tail k16 (raw pos) + fold into running max
            uint32_t a[2][4];
#pragma unroll
            for (int mi = 0; mi < 2; mi++) {
                const int R = wm * 32 + mi * 16 + g;
                uint2 x = *(const uint2*)(smw + TL_W + R * 8 + 2 * tg);
                uint2 y = *(const uint2*)(smw + TL_W + (R + 8) * 8 + 2 * tg);
                a[mi][0] = x.x; a[mi][1] = y.x; a[mi][2] = x.y; a[mi][3] = y.y;
            }
            const uint32_t* bh = smw + BH_W + 16 * 2048;
#pragma unroll
            for (int ni = 0; ni < 8; ni++) {
                uint2 b = *(const uint2*)(bh + (wn * 64 + ni * 8 + g) * 8 + 2 * tg);
                MMA16(acc[0][ni], a[0], b);
                MMA16(acc[1][ni], a[1], b);
            }
#pragma unroll
            for (int ni = 0; ni < 8; ni++)
#pragma unroll
                for (int p = 0; p < 2; p++)
                    rmax[ni][p] = fmaxf(rmax[ni][p],
                        fmaxf(fmaxf(acc[0][ni][p], acc[0][ni][p + 2]),
                              fmaxf(acc[1][ni][p], acc[1][ni][p + 2])));
        }

        if ((i & 15) == 15) {
#pragma unroll
            for (int off = 4; off < 32; off <<= 1)
#pragma unroll
                for (int ni = 0; ni < 8; ni++)
#pragma unroll
                    for (int p = 0; p < 2; p++)
                        rmax[ni][p] = fmaxf(rmax[ni][p],
                                            __shfl_xor_sync(0xffffffffu, rmax[ni][p], off));
            float* red = (float*)(smw + RED_W);
            if (lane < 4) {
#pragma unroll
                for (int ni = 0; ni < 8; ni++)
#pragma unroll
                    for (int p = 0; p < 2; p++)
                        red[wm * 256 + wn * 64 + ni * 8 + 2 * tg + p] = rmax[ni][p];
            }
            __syncthreads();
            if (tid < 256) {
                float v = fmaxf(fmaxf(red[tid], red[256 + tid]),
                                fmaxf(red[512 + tid], red[768 + tid]));
                atomicMax(&g_agg_u[(item >> 3) * 256 + tid], encf(v));
            }
#pragma unroll
            for (int ni = 0; ni < 8; ni++) { rmax[ni][0] = -FLT_MAX; rmax[ni][1] = -FLT_MAX; }
        }
    }
}

// ==================== head: centroid + decode + (b1 - c@W1b) + relu + GEMM2 + sample ====================
__global__ __launch_bounds__(512, 2)
void head_kernel(const float* __restrict__ pos, const float* __restrict__ W1,
                 const float* __restrict__ b1, const float* __restrict__ W2,
                 const float* __restrict__ b2, const float* __restrict__ noise,
                 float* __restrict__ out) {
    const int t = threadIdx.x;
    const int sbase = blockIdx.y * 4;
    __shared__ float ag[4 * 256];
    __shared__ float cw[4][4][3];

    // centroid: 128 threads/scene, 16 pts (48 contiguous floats) each
    {
        const int sl = t >> 7, lt = t & 127;
        const float* p = pos + ((size_t)(sbase + sl) * PTS + (size_t)lt * 16) * 3;
        float s0 = 0.f, s1 = 0.f, s2 = 0.f;
#pragma unroll
        for (int j = 0; j < 12; j++) {
            const float4 f = *(const float4*)(p + j * 4);
            const int m = (4 * j) % 3;
            if (m == 0)      { s0 += f.x + f.w; s1 += f.y; s2 += f.z; }
            else if (m == 1) { s1 += f.x + f.w; s2 += f.y; s0 += f.z; }
            else             { s2 += f.x + f.w; s0 += f.y; s1 += f.z; }
        }
#pragma unroll
        for (int off = 16; off > 0; off >>= 1) {
            s0 += __shfl_xor_sync(0xffffffffu, s0, off);
            s1 += __shfl_xor_sync(0xffffffffu, s1, off);
            s2 += __shfl_xor_sync(0xffffffffu, s2, off);
        }
        if ((t & 31) == 0) {
            const int w = (t >> 5) & 3;
            cw[sl][w][0] = s0; cw[sl][w][1] = s1; cw[sl][w][2] = s2;
        }
    }
    __syncthreads();

    // decode seg-max, add (b1 - c@W1b), relu
#pragma unroll
    for (int jj = 0; jj < 2; jj++) {
        const int e = t + 512 * jj;
        const int sl = e >> 8, k = e & 255;
        const float cx = (cw[sl][0][0] + cw[sl][1][0] + cw[sl][2][0] + cw[sl][3][0]) * (1.f / PTS);
        const float cy = (cw[sl][0][1] + cw[sl][1][1] + cw[sl][2][1] + cw[sl][3][1]) * (1.f / PTS);
        const float cz = (cw[sl][0][2] + cw[sl][1][2] + cw[sl][2][2] + cw[sl][3][2]) * (1.f / PTS);
        const float dlt = b1[k] - (cx * W1[65536 + k] + cy * W1[65792 + k] + cz * W1[66048 + k]);
        const float f = decf(g_agg_u[(sbase + sl) * 256 + k]);
        ag[sl * 256 + k] = fmaxf(f + dlt, 0.f);
    }
    __syncthreads();

    const int col = blockIdx.x * 128 + (t & 127);
    const int sl  = t >> 7;
    const float* a = ag + sl * 256;
    float amu = 0.f, asg = 0.f;
#pragma unroll 8
    for (int k = 0; k < 256; k++) {
        const float av = a[k];
        amu = fmaf(av, W2[(size_t)k * 512 + col], amu);
        asg = fmaf(av, W2[(size_t)k * 512 + col + 256], asg);
    }
    const int s = sbase + sl;
    float mu = amu + b2[col];
    float sr = asg + b2[col + 256];
    float sp = fmaxf(sr, 0.f) + log1pf(expf(-fabsf(sr)));
    out[s * 256 + col] = mu + (sp + 1e-4f) * noise[s * 256 + col];
}

extern "C" void kernel_launch(void* const* d_in, const int* in_sizes, int n_in,
                              void* d_out, int out_size) {
    const float* pos     = (const float*)d_in[0];
    const float* feature = (const float*)d_in[1];
    // d_in[2] = batch: structurally i >> 11, never read
    const float* W1      = (const float*)d_in[3];
    const float* b1      = (const float*)d_in[4];
    const float* W2      = (const float*)d_in[5];
    const float* b2      = (const float*)d_in[6];
    const float* noise   = (const float*)d_in[7];
    float* out = (float*)d_out;

    int nsm = 148;
    if (cudaDeviceGetAttribute(&nsm, cudaDevAttrMultiProcessorCount, 0) != cudaSuccess || nsm < 1)
        nsm = 148;
    if (nsm > NITEMS) nsm = NITEMS;

    cudaFuncSetAttribute(pointconv_kernel,
                         cudaFuncAttributeMaxDynamicSharedMemorySize, SMEM_BYTES);

    prep_kernel<<<168, 256>>>(W1);
    pointconv_kernel<<<nsm, 512, SMEM_BYTES>>>(pos, feature, nsm);
    head_kernel<<<dim3(2, 32), 512>>>(pos, W1, b1, W2, b2, noise, out);
}